// round 8
// baseline (speedup 1.0000x reference)
#include <cuda_runtime.h>
#include <cuda_fp16.h>
#include <stdint.h>

#define N_NODES 100000
#define N_EDGES 1600000
#define D_FEAT  64

// Scratch (device globals — no allocs allowed):
__device__ int    g_row_ptr[N_NODES + 1];
__device__ __half g_emb_h[N_NODES * D_FEAT];   // 12.8 MB fp16 shadow (128B per row)

// Merged prep: fp32->fp16 convert (8 floats/thread) AND CSR boundary fill.
__global__ void prep_kernel(const float* __restrict__ embeds,
                            const int*   __restrict__ rows,
                            int n_edges) {
    int i = blockIdx.x * blockDim.x + threadIdx.x;

    if (i < N_NODES * D_FEAT / 8) {
        const float4* src = reinterpret_cast<const float4*>(embeds) + (size_t)i * 2;
        float4 f0 = src[0];
        float4 f1 = src[1];
        union { __half2 h[4]; uint4 u; } p;
        p.h[0] = __floats2half2_rn(f0.x, f0.y);
        p.h[1] = __floats2half2_rn(f0.z, f0.w);
        p.h[2] = __floats2half2_rn(f1.x, f1.y);
        p.h[3] = __floats2half2_rn(f1.z, f1.w);
        reinterpret_cast<uint4*>(g_emb_h)[i] = p.u;
    }

    if (i < n_edges) {
        int r = rows[i];
        int prev = (i == 0) ? -1 : rows[i - 1];
        for (int rr = prev + 1; rr <= r; ++rr) {
            g_row_ptr[rr] = i;
        }
        if (i == n_edges - 1) {
            for (int rr = r + 1; rr <= N_NODES; ++rr) {
                g_row_ptr[rr] = n_edges;
            }
        }
    }
}

// fp32-exact single-edge accumulate (peel/tail path).
__device__ __forceinline__ void edge_f32(const uint4* __restrict__ emb,
                                         const int* __restrict__ cols,
                                         const float* __restrict__ vals,
                                         int e, int lane8,
                                         float4& aA, float4& aB) {
    int   c = cols[e];
    float v = vals[e];
    uint4 r = emb[(size_t)c * 8 + lane8];
    float2 f0 = __half22float2(*reinterpret_cast<__half2*>(&r.x));
    float2 f1 = __half22float2(*reinterpret_cast<__half2*>(&r.y));
    float2 f2 = __half22float2(*reinterpret_cast<__half2*>(&r.z));
    float2 f3 = __half22float2(*reinterpret_cast<__half2*>(&r.w));
    aA.x += v * f0.x;  aA.y += v * f0.y;
    aA.z += v * f1.x;  aA.w += v * f1.y;
    aB.x += v * f2.x;  aB.y += v * f2.y;
    aB.z += v * f3.x;  aB.w += v * f3.y;
}

// 4-edge half2 micro-kernel: 4 gathers, 4-deep half2 accumulation, fp32 drain.
// Numerically identical depth to R7 (error unchanged).
__device__ __forceinline__ void group4_h2(const uint4* __restrict__ emb,
                                          int c0, int c1, int c2, int c3,
                                          float v0, float v1, float v2, float v3,
                                          int lane8,
                                          float4& aA, float4& aB) {
    uint4 r0 = emb[(size_t)c0 * 8 + lane8];
    uint4 r1 = emb[(size_t)c1 * 8 + lane8];
    uint4 r2 = emb[(size_t)c2 * 8 + lane8];
    uint4 r3 = emb[(size_t)c3 * 8 + lane8];

    __half2 h0 = __float2half2_rn(v0);
    __half2 h1 = __float2half2_rn(v1);
    __half2 h2 = __float2half2_rn(v2);
    __half2 h3 = __float2half2_rn(v3);

    __half2 p0 = __hmul2(h0, *reinterpret_cast<__half2*>(&r0.x));
    __half2 p1 = __hmul2(h0, *reinterpret_cast<__half2*>(&r0.y));
    __half2 p2 = __hmul2(h0, *reinterpret_cast<__half2*>(&r0.z));
    __half2 p3 = __hmul2(h0, *reinterpret_cast<__half2*>(&r0.w));

    p0 = __hfma2(h1, *reinterpret_cast<__half2*>(&r1.x), p0);
    p1 = __hfma2(h1, *reinterpret_cast<__half2*>(&r1.y), p1);
    p2 = __hfma2(h1, *reinterpret_cast<__half2*>(&r1.z), p2);
    p3 = __hfma2(h1, *reinterpret_cast<__half2*>(&r1.w), p3);

    p0 = __hfma2(h2, *reinterpret_cast<__half2*>(&r2.x), p0);
    p1 = __hfma2(h2, *reinterpret_cast<__half2*>(&r2.y), p1);
    p2 = __hfma2(h2, *reinterpret_cast<__half2*>(&r2.z), p2);
    p3 = __hfma2(h2, *reinterpret_cast<__half2*>(&r2.w), p3);

    p0 = __hfma2(h3, *reinterpret_cast<__half2*>(&r3.x), p0);
    p1 = __hfma2(h3, *reinterpret_cast<__half2*>(&r3.y), p1);
    p2 = __hfma2(h3, *reinterpret_cast<__half2*>(&r3.z), p2);
    p3 = __hfma2(h3, *reinterpret_cast<__half2*>(&r3.w), p3);

    float2 f;
    f = __half22float2(p0);  aA.x += f.x;  aA.y += f.y;
    f = __half22float2(p1);  aA.z += f.x;  aA.w += f.y;
    f = __half22float2(p2);  aB.x += f.x;  aB.y += f.y;
    f = __half22float2(p3);  aB.z += f.x;  aB.w += f.y;
}

// SpMM: one quarter-warp (8 lanes) per output row, fp16 table.
// Main loop: 8 edges per iteration = TWO independent 4-deep half2 groups with
// all 8 LDG.128 gathers issued up front (MLP=8 per quarter). Indices loaded
// as int4/float4 (e aligned to 4 via fp32 peel). Drains stay 4-deep -> same
// numerics as the 4-edge version.
__global__ void __launch_bounds__(256) spmm_qwarp_per_row(
    const int*   __restrict__ cols,
    const float* __restrict__ vals,
    float*       __restrict__ out)
{
    int row   = (blockIdx.x * blockDim.x + threadIdx.x) >> 3;
    int lane8 = threadIdx.x & 7;
    if (row >= N_NODES) return;

    int e  = g_row_ptr[row];
    int hi = g_row_ptr[row + 1];

    const uint4* __restrict__ emb = reinterpret_cast<const uint4*>(g_emb_h);

    float4 aA = make_float4(0.f, 0.f, 0.f, 0.f);
    float4 aB = make_float4(0.f, 0.f, 0.f, 0.f);

    // peel to 4-alignment (enables int4/float4 index loads)
    while ((e & 3) && e < hi) {
        edge_f32(emb, cols, vals, e, lane8, aA, aB);
        ++e;
    }

    // main loop: 8 edges, 8 outstanding gathers, two independent 4-deep groups
    for (; e + 7 < hi; e += 8) {
        int4   cA = *reinterpret_cast<const int4*>(cols + e);
        int4   cB = *reinterpret_cast<const int4*>(cols + e + 4);
        float4 vA = *reinterpret_cast<const float4*>(vals + e);
        float4 vB = *reinterpret_cast<const float4*>(vals + e + 4);

        uint4 rA0 = emb[(size_t)cA.x * 8 + lane8];
        uint4 rA1 = emb[(size_t)cA.y * 8 + lane8];
        uint4 rA2 = emb[(size_t)cA.z * 8 + lane8];
        uint4 rA3 = emb[(size_t)cA.w * 8 + lane8];
        uint4 rB0 = emb[(size_t)cB.x * 8 + lane8];
        uint4 rB1 = emb[(size_t)cB.y * 8 + lane8];
        uint4 rB2 = emb[(size_t)cB.z * 8 + lane8];
        uint4 rB3 = emb[(size_t)cB.w * 8 + lane8];

        // group A
        {
            __half2 h0 = __float2half2_rn(vA.x);
            __half2 h1 = __float2half2_rn(vA.y);
            __half2 h2 = __float2half2_rn(vA.z);
            __half2 h3 = __float2half2_rn(vA.w);
            __half2 p0 = __hmul2(h0, *reinterpret_cast<__half2*>(&rA0.x));
            __half2 p1 = __hmul2(h0, *reinterpret_cast<__half2*>(&rA0.y));
            __half2 p2 = __hmul2(h0, *reinterpret_cast<__half2*>(&rA0.z));
            __half2 p3 = __hmul2(h0, *reinterpret_cast<__half2*>(&rA0.w));
            p0 = __hfma2(h1, *reinterpret_cast<__half2*>(&rA1.x), p0);
            p1 = __hfma2(h1, *reinterpret_cast<__half2*>(&rA1.y), p1);
            p2 = __hfma2(h1, *reinterpret_cast<__half2*>(&rA1.z), p2);
            p3 = __hfma2(h1, *reinterpret_cast<__half2*>(&rA1.w), p3);
            p0 = __hfma2(h2, *reinterpret_cast<__half2*>(&rA2.x), p0);
            p1 = __hfma2(h2, *reinterpret_cast<__half2*>(&rA2.y), p1);
            p2 = __hfma2(h2, *reinterpret_cast<__half2*>(&rA2.z), p2);
            p3 = __hfma2(h2, *reinterpret_cast<__half2*>(&rA2.w), p3);
            p0 = __hfma2(h3, *reinterpret_cast<__half2*>(&rA3.x), p0);
            p1 = __hfma2(h3, *reinterpret_cast<__half2*>(&rA3.y), p1);
            p2 = __hfma2(h3, *reinterpret_cast<__half2*>(&rA3.z), p2);
            p3 = __hfma2(h3, *reinterpret_cast<__half2*>(&rA3.w), p3);
            float2 f;
            f = __half22float2(p0);  aA.x += f.x;  aA.y += f.y;
            f = __half22float2(p1);  aA.z += f.x;  aA.w += f.y;
            f = __half22float2(p2);  aB.x += f.x;  aB.y += f.y;
            f = __half22float2(p3);  aB.z += f.x;  aB.w += f.y;
        }
        // group B (independent 4-deep accumulation)
        {
            __half2 h0 = __float2half2_rn(vB.x);
            __half2 h1 = __float2half2_rn(vB.y);
            __half2 h2 = __float2half2_rn(vB.z);
            __half2 h3 = __float2half2_rn(vB.w);
            __half2 p0 = __hmul2(h0, *reinterpret_cast<__half2*>(&rB0.x));
            __half2 p1 = __hmul2(h0, *reinterpret_cast<__half2*>(&rB0.y));
            __half2 p2 = __hmul2(h0, *reinterpret_cast<__half2*>(&rB0.z));
            __half2 p3 = __hmul2(h0, *reinterpret_cast<__half2*>(&rB0.w));
            p0 = __hfma2(h1, *reinterpret_cast<__half2*>(&rB1.x), p0);
            p1 = __hfma2(h1, *reinterpret_cast<__half2*>(&rB1.y), p1);
            p2 = __hfma2(h1, *reinterpret_cast<__half2*>(&rB1.z), p2);
            p3 = __hfma2(h1, *reinterpret_cast<__half2*>(&rB1.w), p3);
            p0 = __hfma2(h2, *reinterpret_cast<__half2*>(&rB2.x), p0);
            p1 = __hfma2(h2, *reinterpret_cast<__half2*>(&rB2.y), p1);
            p2 = __hfma2(h2, *reinterpret_cast<__half2*>(&rB2.z), p2);
            p3 = __hfma2(h2, *reinterpret_cast<__half2*>(&rB2.w), p3);
            p0 = __hfma2(h3, *reinterpret_cast<__half2*>(&rB3.x), p0);
            p1 = __hfma2(h3, *reinterpret_cast<__half2*>(&rB3.y), p1);
            p2 = __hfma2(h3, *reinterpret_cast<__half2*>(&rB3.z), p2);
            p3 = __hfma2(h3, *reinterpret_cast<__half2*>(&rB3.w), p3);
            float2 f;
            f = __half22float2(p0);  aA.x += f.x;  aA.y += f.y;
            f = __half22float2(p1);  aA.z += f.x;  aA.w += f.y;
            f = __half22float2(p2);  aB.x += f.x;  aB.y += f.y;
            f = __half22float2(p3);  aB.z += f.x;  aB.w += f.y;
        }
    }

    // 4-edge half2 group if available
    if (e + 3 < hi) {
        int4   c4 = *reinterpret_cast<const int4*>(cols + e);
        float4 v4 = *reinterpret_cast<const float4*>(vals + e);
        group4_h2(emb, c4.x, c4.y, c4.z, c4.w, v4.x, v4.y, v4.z, v4.w,
                  lane8, aA, aB);
        e += 4;
    }
    // tail (<=3 edges): exact fp32 path
    for (; e < hi; ++e) {
        edge_f32(emb, cols, vals, e, lane8, aA, aB);
    }

    // 8 lanes x 32B = 256B coalesced output row
    float4* o = reinterpret_cast<float4*>(out) + (size_t)row * 16 + lane8 * 2;
    o[0] = aA;
    o[1] = aB;
}

extern "C" void kernel_launch(void* const* d_in, const int* in_sizes, int n_in,
                              void* d_out, int out_size) {
    const int*   rows   = (const int*)d_in[0];
    const int*   cols   = (const int*)d_in[1];
    const float* vals   = (const float*)d_in[2];
    const float* embeds = (const float*)d_in[3];
    float*       out    = (float*)d_out;

    int n_edges = in_sizes[0];

    {
        int total = n_edges;  // 1.6M >= N_NODES*D_FEAT/8 (800k)
        int threads = 256;
        prep_kernel<<<(total + threads - 1) / threads, threads>>>(embeds, rows, n_edges);
    }
    {
        int threads = 256;
        int blocks = (N_NODES * 8 + threads - 1) / threads;
        spmm_qwarp_per_row<<<blocks, threads>>>(cols, vals, out);
    }
}

// round 9
// speedup vs baseline: 1.0417x; 1.0417x over previous
#include <cuda_runtime.h>
#include <cuda_fp16.h>
#include <stdint.h>

#define N_NODES 100000
#define N_EDGES 1600000
#define D_FEAT  64

// Scratch (device globals — no allocs allowed):
__device__ int    g_row_ptr[N_NODES + 1];
__device__ __half g_emb_h[N_NODES * D_FEAT];                  // 12.8 MB fp16 table
__device__ __align__(16) __half2 g_vals_h2[N_EDGES];          // 6.4 MB splat(v,v) table

// Merged prep: fp32->fp16 embed convert, vals->half2 splat, CSR boundary fill.
__global__ void prep_kernel(const float* __restrict__ embeds,
                            const float* __restrict__ vals,
                            const int*   __restrict__ rows,
                            int n_edges) {
    int i = blockIdx.x * blockDim.x + threadIdx.x;

    // Task 1: convert 8 embed floats -> 8 halfs
    if (i < N_NODES * D_FEAT / 8) {
        const float4* src = reinterpret_cast<const float4*>(embeds) + (size_t)i * 2;
        float4 f0 = src[0];
        float4 f1 = src[1];
        union { __half2 h[4]; uint4 u; } p;
        p.h[0] = __floats2half2_rn(f0.x, f0.y);
        p.h[1] = __floats2half2_rn(f0.z, f0.w);
        p.h[2] = __floats2half2_rn(f1.x, f1.y);
        p.h[3] = __floats2half2_rn(f1.z, f1.w);
        reinterpret_cast<uint4*>(g_emb_h)[i] = p.u;
    }

    // Task 2: splat 4 vals -> 4 half2(v,v)
    if (i < n_edges / 4) {
        float4 v = reinterpret_cast<const float4*>(vals)[i];
        union { __half2 h[4]; uint4 u; } s;
        s.h[0] = __float2half2_rn(v.x);
        s.h[1] = __float2half2_rn(v.y);
        s.h[2] = __float2half2_rn(v.z);
        s.h[3] = __float2half2_rn(v.w);
        reinterpret_cast<uint4*>(g_vals_h2)[i] = s.u;
    }
    // leftover vals (n_edges % 4)
    if (i >= n_edges / 4 * 4 && i < n_edges) {
        g_vals_h2[i] = __float2half2_rn(vals[i]);
    }

    // Task 3: row_ptr boundary fill (rows sorted)
    if (i < n_edges) {
        int r = rows[i];
        int prev = (i == 0) ? -1 : rows[i - 1];
        for (int rr = prev + 1; rr <= r; ++rr) {
            g_row_ptr[rr] = i;
        }
        if (i == n_edges - 1) {
            for (int rr = r + 1; rr <= N_NODES; ++rr) {
                g_row_ptr[rr] = n_edges;
            }
        }
    }
}

// fp32-exact single-edge accumulate (peel/tail, <=2 edges per row).
__device__ __forceinline__ void edge_f32(const uint4* __restrict__ emb,
                                         const int* __restrict__ cols,
                                         const float* __restrict__ vals,
                                         int e, int lane8,
                                         float4& aA, float4& aB) {
    int   c = cols[e];
    float v = vals[e];
    uint4 r = emb[(size_t)c * 8 + lane8];
    float2 f0 = __half22float2(*reinterpret_cast<__half2*>(&r.x));
    float2 f1 = __half22float2(*reinterpret_cast<__half2*>(&r.y));
    float2 f2 = __half22float2(*reinterpret_cast<__half2*>(&r.z));
    float2 f3 = __half22float2(*reinterpret_cast<__half2*>(&r.w));
    aA.x += v * f0.x;  aA.y += v * f0.y;
    aA.z += v * f1.x;  aA.w += v * f1.y;
    aB.x += v * f2.x;  aB.y += v * f2.y;
    aB.z += v * f3.x;  aB.w += v * f3.y;
}

// 4-edge half2 group: gathers r0..r3, splatted h0..h3, 4-deep half2 accum,
// fp32 drain. Same numerics as R7.
__device__ __forceinline__ void group4(const uint4& r0, const uint4& r1,
                                       const uint4& r2, const uint4& r3,
                                       __half2 h0, __half2 h1,
                                       __half2 h2, __half2 h3,
                                       float4& aA, float4& aB) {
    __half2 p0 = __hmul2(h0, *reinterpret_cast<const __half2*>(&r0.x));
    __half2 p1 = __hmul2(h0, *reinterpret_cast<const __half2*>(&r0.y));
    __half2 p2 = __hmul2(h0, *reinterpret_cast<const __half2*>(&r0.z));
    __half2 p3 = __hmul2(h0, *reinterpret_cast<const __half2*>(&r0.w));
    p0 = __hfma2(h1, *reinterpret_cast<const __half2*>(&r1.x), p0);
    p1 = __hfma2(h1, *reinterpret_cast<const __half2*>(&r1.y), p1);
    p2 = __hfma2(h1, *reinterpret_cast<const __half2*>(&r1.z), p2);
    p3 = __hfma2(h1, *reinterpret_cast<const __half2*>(&r1.w), p3);
    p0 = __hfma2(h2, *reinterpret_cast<const __half2*>(&r2.x), p0);
    p1 = __hfma2(h2, *reinterpret_cast<const __half2*>(&r2.y), p1);
    p2 = __hfma2(h2, *reinterpret_cast<const __half2*>(&r2.z), p2);
    p3 = __hfma2(h2, *reinterpret_cast<const __half2*>(&r2.w), p3);
    p0 = __hfma2(h3, *reinterpret_cast<const __half2*>(&r3.x), p0);
    p1 = __hfma2(h3, *reinterpret_cast<const __half2*>(&r3.y), p1);
    p2 = __hfma2(h3, *reinterpret_cast<const __half2*>(&r3.z), p2);
    p3 = __hfma2(h3, *reinterpret_cast<const __half2*>(&r3.w), p3);
    float2 f;
    f = __half22float2(p0);  aA.x += f.x;  aA.y += f.y;
    f = __half22float2(p1);  aA.z += f.x;  aA.w += f.y;
    f = __half22float2(p2);  aB.x += f.x;  aB.y += f.y;
    f = __half22float2(p3);  aB.z += f.x;  aB.w += f.y;
}

// SpMM: one quarter-warp (8 lanes) per output row, fp16 table, splatted vals.
// Odd-peel (<=1 scalar edge) -> all packed loads are int2/uint2 (8B aligned).
// Main loop: 8 edges = two independent 4-deep half2 groups, 8 outstanding
// LDG.128 gathers. Tail: 4-group, then 2-group, then <=1 scalar edge.
__global__ void __launch_bounds__(128) spmm_qwarp_per_row(
    const int*   __restrict__ cols,
    const float* __restrict__ vals,
    float*       __restrict__ out)
{
    int row   = (blockIdx.x * blockDim.x + threadIdx.x) >> 3;
    int lane8 = threadIdx.x & 7;
    if (row >= N_NODES) return;

    int e  = g_row_ptr[row];
    int hi = g_row_ptr[row + 1];

    const uint4* __restrict__ emb = reinterpret_cast<const uint4*>(g_emb_h);

    float4 aA = make_float4(0.f, 0.f, 0.f, 0.f);
    float4 aB = make_float4(0.f, 0.f, 0.f, 0.f);

    // peel to even alignment (<=1 edge, exact fp32 path)
    if ((e & 1) && e < hi) {
        edge_f32(emb, cols, vals, e, lane8, aA, aB);
        ++e;
    }

    // main loop: 8 edges, 8 outstanding gathers, two independent 4-deep groups
    for (; e + 7 < hi; e += 8) {
        int2 c01 = *reinterpret_cast<const int2*>(cols + e);
        int2 c23 = *reinterpret_cast<const int2*>(cols + e + 2);
        int2 c45 = *reinterpret_cast<const int2*>(cols + e + 4);
        int2 c67 = *reinterpret_cast<const int2*>(cols + e + 6);
        uint2 w01 = *reinterpret_cast<const uint2*>(g_vals_h2 + e);
        uint2 w23 = *reinterpret_cast<const uint2*>(g_vals_h2 + e + 2);
        uint2 w45 = *reinterpret_cast<const uint2*>(g_vals_h2 + e + 4);
        uint2 w67 = *reinterpret_cast<const uint2*>(g_vals_h2 + e + 6);

        uint4 r0 = emb[(size_t)c01.x * 8 + lane8];
        uint4 r1 = emb[(size_t)c01.y * 8 + lane8];
        uint4 r2 = emb[(size_t)c23.x * 8 + lane8];
        uint4 r3 = emb[(size_t)c23.y * 8 + lane8];
        uint4 r4 = emb[(size_t)c45.x * 8 + lane8];
        uint4 r5 = emb[(size_t)c45.y * 8 + lane8];
        uint4 r6 = emb[(size_t)c67.x * 8 + lane8];
        uint4 r7 = emb[(size_t)c67.y * 8 + lane8];

        group4(r0, r1, r2, r3,
               *reinterpret_cast<__half2*>(&w01.x),
               *reinterpret_cast<__half2*>(&w01.y),
               *reinterpret_cast<__half2*>(&w23.x),
               *reinterpret_cast<__half2*>(&w23.y), aA, aB);
        group4(r4, r5, r6, r7,
               *reinterpret_cast<__half2*>(&w45.x),
               *reinterpret_cast<__half2*>(&w45.y),
               *reinterpret_cast<__half2*>(&w67.x),
               *reinterpret_cast<__half2*>(&w67.y), aA, aB);
    }

    // tail: one 4-edge group
    if (e + 3 < hi) {
        int2 c01 = *reinterpret_cast<const int2*>(cols + e);
        int2 c23 = *reinterpret_cast<const int2*>(cols + e + 2);
        uint2 w01 = *reinterpret_cast<const uint2*>(g_vals_h2 + e);
        uint2 w23 = *reinterpret_cast<const uint2*>(g_vals_h2 + e + 2);
        uint4 r0 = emb[(size_t)c01.x * 8 + lane8];
        uint4 r1 = emb[(size_t)c01.y * 8 + lane8];
        uint4 r2 = emb[(size_t)c23.x * 8 + lane8];
        uint4 r3 = emb[(size_t)c23.y * 8 + lane8];
        group4(r0, r1, r2, r3,
               *reinterpret_cast<__half2*>(&w01.x),
               *reinterpret_cast<__half2*>(&w01.y),
               *reinterpret_cast<__half2*>(&w23.x),
               *reinterpret_cast<__half2*>(&w23.y), aA, aB);
        e += 4;
    }
    // tail: one 2-edge half2 group
    if (e + 1 < hi) {
        int2  c01 = *reinterpret_cast<const int2*>(cols + e);
        uint2 w01 = *reinterpret_cast<const uint2*>(g_vals_h2 + e);
        uint4 r0 = emb[(size_t)c01.x * 8 + lane8];
        uint4 r1 = emb[(size_t)c01.y * 8 + lane8];
        __half2 h0 = *reinterpret_cast<__half2*>(&w01.x);
        __half2 h1 = *reinterpret_cast<__half2*>(&w01.y);
        __half2 p0 = __hmul2(h0, *reinterpret_cast<__half2*>(&r0.x));
        __half2 p1 = __hmul2(h0, *reinterpret_cast<__half2*>(&r0.y));
        __half2 p2 = __hmul2(h0, *reinterpret_cast<__half2*>(&r0.z));
        __half2 p3 = __hmul2(h0, *reinterpret_cast<__half2*>(&r0.w));
        p0 = __hfma2(h1, *reinterpret_cast<__half2*>(&r1.x), p0);
        p1 = __hfma2(h1, *reinterpret_cast<__half2*>(&r1.y), p1);
        p2 = __hfma2(h1, *reinterpret_cast<__half2*>(&r1.z), p2);
        p3 = __hfma2(h1, *reinterpret_cast<__half2*>(&r1.w), p3);
        float2 f;
        f = __half22float2(p0);  aA.x += f.x;  aA.y += f.y;
        f = __half22float2(p1);  aA.z += f.x;  aA.w += f.y;
        f = __half22float2(p2);  aB.x += f.x;  aB.y += f.y;
        f = __half22float2(p3);  aB.z += f.x;  aB.w += f.y;
        e += 2;
    }
    // tail: final scalar edge (exact fp32)
    if (e < hi) {
        edge_f32(emb, cols, vals, e, lane8, aA, aB);
    }

    // 8 lanes x 32B = 256B coalesced output row
    float4* o = reinterpret_cast<float4*>(out) + (size_t)row * 16 + lane8 * 2;
    o[0] = aA;
    o[1] = aB;
}

extern "C" void kernel_launch(void* const* d_in, const int* in_sizes, int n_in,
                              void* d_out, int out_size) {
    const int*   rows   = (const int*)d_in[0];
    const int*   cols   = (const int*)d_in[1];
    const float* vals   = (const float*)d_in[2];
    const float* embeds = (const float*)d_in[3];
    float*       out    = (float*)d_out;

    int n_edges = in_sizes[0];

    {
        int total = n_edges;
        int threads = 256;
        prep_kernel<<<(total + threads - 1) / threads, threads>>>(embeds, vals, rows, n_edges);
    }
    {
        int threads = 128;
        int blocks = (N_NODES * 8 + threads - 1) / threads;
        spmm_qwarp_per_row<<<blocks, threads>>>(cols, vals, out);
    }
}

// round 10
// speedup vs baseline: 1.0974x; 1.0535x over previous
#include <cuda_runtime.h>
#include <cuda_fp16.h>
#include <stdint.h>

#define N_NODES 100000
#define N_EDGES 1600000
#define D_FEAT  64

// Scratch (device globals — no allocs allowed):
__device__ int    g_row_ptr[N_NODES + 1];
__device__ __half g_emb_h[N_NODES * D_FEAT];   // 12.8 MB fp16 shadow (128B per row)

// Merged prep: fp32->fp16 convert (8 floats/thread) AND CSR boundary fill.
__global__ void prep_kernel(const float* __restrict__ embeds,
                            const int*   __restrict__ rows,
                            int n_edges) {
    int i = blockIdx.x * blockDim.x + threadIdx.x;

    if (i < N_NODES * D_FEAT / 8) {
        const float4* src = reinterpret_cast<const float4*>(embeds) + (size_t)i * 2;
        float4 f0 = src[0];
        float4 f1 = src[1];
        union { __half2 h[4]; uint4 u; } p;
        p.h[0] = __floats2half2_rn(f0.x, f0.y);
        p.h[1] = __floats2half2_rn(f0.z, f0.w);
        p.h[2] = __floats2half2_rn(f1.x, f1.y);
        p.h[3] = __floats2half2_rn(f1.z, f1.w);
        reinterpret_cast<uint4*>(g_emb_h)[i] = p.u;
    }

    if (i < n_edges) {
        int r = rows[i];
        int prev = (i == 0) ? -1 : rows[i - 1];
        for (int rr = prev + 1; rr <= r; ++rr) {
            g_row_ptr[rr] = i;
        }
        if (i == n_edges - 1) {
            for (int rr = r + 1; rr <= N_NODES; ++rr) {
                g_row_ptr[rr] = n_edges;
            }
        }
    }
}

// fp32-exact single-edge accumulate (peel/tail path).
__device__ __forceinline__ void edge_f32(const uint4* __restrict__ emb,
                                         const int* __restrict__ cols,
                                         const float* __restrict__ vals,
                                         int e, int lane8,
                                         float4& aA, float4& aB) {
    int   c = cols[e];
    float v = vals[e];
    uint4 r = emb[(size_t)c * 8 + lane8];
    float2 f0 = __half22float2(*reinterpret_cast<__half2*>(&r.x));
    float2 f1 = __half22float2(*reinterpret_cast<__half2*>(&r.y));
    float2 f2 = __half22float2(*reinterpret_cast<__half2*>(&r.z));
    float2 f3 = __half22float2(*reinterpret_cast<__half2*>(&r.w));
    aA.x += v * f0.x;  aA.y += v * f0.y;
    aA.z += v * f1.x;  aA.w += v * f1.y;
    aB.x += v * f2.x;  aB.y += v * f2.y;
    aB.z += v * f3.x;  aB.w += v * f3.y;
}

// 4-edge half2 chain, NO drain: returns the 4-deep half2 partials in p0..p3.
__device__ __forceinline__ void chain4(const uint4* __restrict__ emb,
                                       const int* __restrict__ cols,
                                       const float* __restrict__ vals,
                                       int e, int lane8,
                                       __half2& p0, __half2& p1,
                                       __half2& p2, __half2& p3) {
    int2   c01 = *reinterpret_cast<const int2*>(cols + e);
    int2   c23 = *reinterpret_cast<const int2*>(cols + e + 2);
    float2 v01 = *reinterpret_cast<const float2*>(vals + e);
    float2 v23 = *reinterpret_cast<const float2*>(vals + e + 2);

    uint4 r0 = emb[(size_t)c01.x * 8 + lane8];
    uint4 r1 = emb[(size_t)c01.y * 8 + lane8];
    uint4 r2 = emb[(size_t)c23.x * 8 + lane8];
    uint4 r3 = emb[(size_t)c23.y * 8 + lane8];

    __half2 h0 = __float2half2_rn(v01.x);
    __half2 h1 = __float2half2_rn(v01.y);
    __half2 h2 = __float2half2_rn(v23.x);
    __half2 h3 = __float2half2_rn(v23.y);

    p0 = __hmul2(h0, *reinterpret_cast<__half2*>(&r0.x));
    p1 = __hmul2(h0, *reinterpret_cast<__half2*>(&r0.y));
    p2 = __hmul2(h0, *reinterpret_cast<__half2*>(&r0.z));
    p3 = __hmul2(h0, *reinterpret_cast<__half2*>(&r0.w));

    p0 = __hfma2(h1, *reinterpret_cast<__half2*>(&r1.x), p0);
    p1 = __hfma2(h1, *reinterpret_cast<__half2*>(&r1.y), p1);
    p2 = __hfma2(h1, *reinterpret_cast<__half2*>(&r1.z), p2);
    p3 = __hfma2(h1, *reinterpret_cast<__half2*>(&r1.w), p3);

    p0 = __hfma2(h2, *reinterpret_cast<__half2*>(&r2.x), p0);
    p1 = __hfma2(h2, *reinterpret_cast<__half2*>(&r2.y), p1);
    p2 = __hfma2(h2, *reinterpret_cast<__half2*>(&r2.z), p2);
    p3 = __hfma2(h2, *reinterpret_cast<__half2*>(&r2.w), p3);

    p0 = __hfma2(h3, *reinterpret_cast<__half2*>(&r3.x), p0);
    p1 = __hfma2(h3, *reinterpret_cast<__half2*>(&r3.y), p1);
    p2 = __hfma2(h3, *reinterpret_cast<__half2*>(&r3.z), p2);
    p3 = __hfma2(h3, *reinterpret_cast<__half2*>(&r3.w), p3);
}

// drain 4 half2 partials into the fp32 accumulators (8 CVT + 8 FADD)
__device__ __forceinline__ void drain(__half2 p0, __half2 p1,
                                      __half2 p2, __half2 p3,
                                      float4& aA, float4& aB) {
    float2 f;
    f = __half22float2(p0);  aA.x += f.x;  aA.y += f.y;
    f = __half22float2(p1);  aA.z += f.x;  aA.w += f.y;
    f = __half22float2(p2);  aB.x += f.x;  aB.y += f.y;
    f = __half22float2(p3);  aB.z += f.x;  aB.w += f.y;
}

// SpMM: one quarter-warp (8 lanes) per output row, fp16 table.
// Main loop: 8 edges = two sequential 4-deep half2 chains (gather regs stay
// at 4 uint4 -> no ptxas serialization), combined with 4 HADD2 and drained
// ONCE -> CVT cost halves to 1/edge. Tail: one 4-chain + <=3 fp32 edges.
__global__ void __launch_bounds__(256) spmm_qwarp_per_row(
    const int*   __restrict__ cols,
    const float* __restrict__ vals,
    float*       __restrict__ out)
{
    int row   = (blockIdx.x * blockDim.x + threadIdx.x) >> 3;
    int lane8 = threadIdx.x & 7;
    if (row >= N_NODES) return;

    int e  = g_row_ptr[row];
    int hi = g_row_ptr[row + 1];

    const uint4* __restrict__ emb = reinterpret_cast<const uint4*>(g_emb_h);

    float4 aA = make_float4(0.f, 0.f, 0.f, 0.f);
    float4 aB = make_float4(0.f, 0.f, 0.f, 0.f);

    // peel to even alignment (<=1 edge, exact fp32 path)
    if ((e & 1) && e < hi) {
        edge_f32(emb, cols, vals, e, lane8, aA, aB);
        ++e;
    }

    // main loop: 8 edges, two 4-deep chains, one HADD2-combined drain
    for (; e + 7 < hi; e += 8) {
        __half2 p0, p1, p2, p3;
        chain4(emb, cols, vals, e, lane8, p0, p1, p2, p3);
        __half2 q0, q1, q2, q3;
        chain4(emb, cols, vals, e + 4, lane8, q0, q1, q2, q3);
        p0 = __hadd2(p0, q0);
        p1 = __hadd2(p1, q1);
        p2 = __hadd2(p2, q2);
        p3 = __hadd2(p3, q3);
        drain(p0, p1, p2, p3, aA, aB);
    }

    // tail: one 4-edge chain with direct drain
    if (e + 3 < hi) {
        __half2 p0, p1, p2, p3;
        chain4(emb, cols, vals, e, lane8, p0, p1, p2, p3);
        drain(p0, p1, p2, p3, aA, aB);
        e += 4;
    }
    // tail: <=3 scalar edges (exact fp32)
    for (; e < hi; ++e) {
        edge_f32(emb, cols, vals, e, lane8, aA, aB);
    }

    // 8 lanes x 32B = 256B coalesced output row
    float4* o = reinterpret_cast<float4*>(out) + (size_t)row * 16 + lane8 * 2;
    o[0] = aA;
    o[1] = aB;
}

extern "C" void kernel_launch(void* const* d_in, const int* in_sizes, int n_in,
                              void* d_out, int out_size) {
    const int*   rows   = (const int*)d_in[0];
    const int*   cols   = (const int*)d_in[1];
    const float* vals   = (const float*)d_in[2];
    const float* embeds = (const float*)d_in[3];
    float*       out    = (float*)d_out;

    int n_edges = in_sizes[0];

    {
        int total = n_edges;
        int threads = 256;
        prep_kernel<<<(total + threads - 1) / threads, threads>>>(embeds, rows, n_edges);
    }
    {
        int threads = 256;
        int blocks = (N_NODES * 8 + threads - 1) / threads;
        spmm_qwarp_per_row<<<blocks, threads>>>(cols, vals, out);
    }
}